// round 11
// baseline (speedup 1.0000x reference)
#include <cuda_runtime.h>
#include <cuda_fp16.h>
#include <math.h>
#include <string.h>

#define NB 4
#define NP 2048
#define ND 64
#define EPS_F 0.1f
#define IEPS 10.0f
#define THRESH_F 0.1f
#define MAX_ITER 50
#define SKIP_T 22.0f
#define LMU (-7.6245985f)   // log(1/2048 + 1e-8)

// D[b][i][j] = 2 * <x_bi, y_bj>  fp16 (32 MB). All sweeps touch only D.
static __device__ __half g_D[(size_t)NB * NP * NP];
static __device__ float g_nx[NB * NP], g_ny[NB * NP];
static __device__ float g_p[NB * NP];          // p = (u - nx)/eps
static __device__ float g_q[NB * NP];          // q = (v - ny)/eps
static __device__ float g_qm[2][NB * NP];      // col-pass partial max
static __device__ float g_qs[2][NB * NP];      // col-pass partial sum
static __device__ float g_errpart[1024];
static __device__ float g_costpart[1024];
static __device__ int   g_done;

__device__ __forceinline__ float2 h2f(unsigned u) {
    __half2 h; memcpy(&h, &u, 4);
    return __half22float2(h);
}
__device__ __forceinline__ __half2 u2h(unsigned u) {
    __half2 h; memcpy(&h, &u, 4);
    return h;
}

// ---------------------------------------------------------------------------
// squared norms; warp per row, 16384 warps (x then y)
// ---------------------------------------------------------------------------
__global__ __launch_bounds__(256) void k_nxny(const float* __restrict__ x,
                                              const float* __restrict__ y) {
    int gw   = (blockIdx.x * 256 + threadIdx.x) >> 5;
    int lane = threadIdx.x & 31;
    const float* src = (gw < NB * NP) ? x + (size_t)gw * ND
                                      : y + (size_t)(gw - NB * NP) * ND;
    float2 v = ((const float2*)src)[lane];
    float s = v.x * v.x + v.y * v.y;
    #pragma unroll
    for (int off = 16; off; off >>= 1)
        s += __shfl_down_sync(0xffffffffu, s, off);
    if (lane == 0) {
        if (gw < NB * NP) g_nx[gw] = s;
        else              g_ny[gw - NB * NP] = s;
    }
}

// init (after k_nxny): u=v=0  ->  p = -10*nx, q = -10*ny
__global__ void k_init() {
    int t = blockIdx.x * blockDim.x + threadIdx.x;
    if (t < NB * NP) {
        g_p[t] = -IEPS * g_nx[t];
        g_q[t] = -IEPS * g_ny[t];
    }
    if (t == 0) g_done = 0;
}

// ---------------------------------------------------------------------------
// D = 2<x,y> fp16; grid (32,32,4), 256 thr, 64x64 tile
// ---------------------------------------------------------------------------
__global__ __launch_bounds__(256) void k_costd(const float* __restrict__ x,
                                               const float* __restrict__ y) {
    __shared__ __align__(16) float xs[ND][68];
    __shared__ __align__(16) float ys[ND][68];

    int b  = blockIdx.z;
    int i0 = blockIdx.y * 64;
    int j0 = blockIdx.x * 64;
    int tid = threadIdx.x;

    const float* xp = x + ((size_t)b * NP + i0) * ND;
    const float* yp = y + ((size_t)b * NP + j0) * ND;

    for (int idx = tid; idx < 64 * ND; idx += 256) {
        int r = idx >> 6;
        int d = idx & 63;
        xs[d][r] = xp[r * ND + d];
        ys[d][r] = yp[r * ND + d];
    }
    __syncthreads();

    int tx = tid & 15, ty = tid >> 4;
    float acc[4][4] = {};
    #pragma unroll 16
    for (int d = 0; d < ND; d++) {
        float4 xr = *(const float4*)&xs[d][ty * 4];
        float4 yr = *(const float4*)&ys[d][tx * 4];
        float xa[4] = {xr.x, xr.y, xr.z, xr.w};
        float ya[4] = {yr.x, yr.y, yr.z, yr.w};
        #pragma unroll
        for (int a = 0; a < 4; a++)
            #pragma unroll
            for (int c = 0; c < 4; c++)
                acc[a][c] = fmaf(xa[a], ya[c], acc[a][c]);
    }

    #pragma unroll
    for (int a = 0; a < 4; a++) {
        int i = i0 + ty * 4 + a;
        size_t base = ((size_t)b * NP + i) * NP + j0 + tx * 4;
        __half2 h01 = __floats2half2_rn(2.0f * acc[a][0], 2.0f * acc[a][1]);
        __half2 h23 = __floats2half2_rn(2.0f * acc[a][2], 2.0f * acc[a][3]);
        uint2 o;
        memcpy(&o.x, &h01, 4);
        memcpy(&o.y, &h23, 4);
        *(uint2*)(g_D + base) = o;
    }
}

// ---------------------------------------------------------------------------
// row pass: p_new_i = LMU - LSE_j(q_j + 10*D_ij)
// grid 1024 x 256, warp/row.
// Pass A: fp16x2 max scan (HFMA2/HMAX2), loads consumed immediately.
// Pass B: fp32 exp only on 256-col stripes within SKIP_T of the row max;
//         D reloaded via __ldg (L1-hot).
// ---------------------------------------------------------------------------
__global__ __launch_bounds__(256) void k_prow() {
    if (*(volatile int*)&g_done) return;
    __shared__ __align__(16) float    qs[NP];        // fp32 q (pass B)
    __shared__ __align__(16) unsigned qh[NP / 2];    // half2 q (pass A)
    __shared__ float werr[8];

    int tid = threadIdx.x;
    int rowbase = blockIdx.x * 8;
    int b = rowbase >> 11;

    {   // coalesced q load + half2 mirror
        const float4* src = (const float4*)(g_q + b * NP);
        #pragma unroll
        for (int k = 0; k < 2; k++) {
            float4 v = src[tid + k * 256];
            ((float4*)qs)[tid + k * 256] = v;
            __half2 h01 = __floats2half2_rn(v.x, v.y);
            __half2 h23 = __floats2half2_rn(v.z, v.w);
            uint2 o;
            memcpy(&o.x, &h01, 4);
            memcpy(&o.y, &h23, 4);
            ((uint2*)qh)[tid + k * 256] = o;
        }
    }
    __syncthreads();

    int w = tid >> 5, lane = tid & 31;
    int row = rowbase + w;
    const uint4* Dr  = (const uint4*)(g_D + (size_t)row * NP);
    const uint4* qh4 = (const uint4*)qh;    // uint4 = 8 halves, same tiling as Dr
    const float4* qv = (const float4*)qs;

    const __half2 ieps2 = __floats2half2_rn(IEPS, IEPS);

    // pass A: per-chunk approximate max in fp16
    float cmf[8];
    float m = -INFINITY;
    #pragma unroll 1
    for (int g = 0; g < 2; g++) {
        #pragma unroll
        for (int kk = 0; kk < 4; kk++) {
            int k = g * 4 + kk;
            uint4 L = __ldg(Dr + k * 32 + lane);
            uint4 Q = qh4[k * 32 + lane];
            __half2 a0 = __hfma2(u2h(L.x), ieps2, u2h(Q.x));
            __half2 a1 = __hfma2(u2h(L.y), ieps2, u2h(Q.y));
            __half2 a2 = __hfma2(u2h(L.z), ieps2, u2h(Q.z));
            __half2 a3 = __hfma2(u2h(L.w), ieps2, u2h(Q.w));
            __half2 c  = __hmax2(__hmax2(a0, a1), __hmax2(a2, a3));
            float cf = fmaxf(__low2float(c), __high2float(c));
            cmf[k] = cf;
            m = fmaxf(m, cf);
        }
    }
    #pragma unroll
    for (int off = 16; off; off >>= 1)
        m = fmaxf(m, __shfl_xor_sync(0xffffffffu, m, off));
    m += 1.0f;   // fp16 max may undershoot true max by rounding; pad for safety

    // pass B: fp32 selective exp (D reloaded; L1-hot)
    float s = 0.0f;
    float thr = m - SKIP_T;
    #pragma unroll 1
    for (int k = 0; k < 8; k++) {
        if (__any_sync(0xffffffffu, cmf[k] > thr)) {
            uint4 L = __ldg(Dr + k * 32 + lane);
            int qi = (k * 32 + lane) * 2;
            float4 q0 = qv[qi], q1 = qv[qi + 1];
            float2 f0 = h2f(L.x), f1 = h2f(L.y);
            float2 f2 = h2f(L.z), f3 = h2f(L.w);
            s += __expf(fmaf(f0.x, IEPS, q0.x) - m);
            s += __expf(fmaf(f0.y, IEPS, q0.y) - m);
            s += __expf(fmaf(f1.x, IEPS, q0.z) - m);
            s += __expf(fmaf(f1.y, IEPS, q0.w) - m);
            s += __expf(fmaf(f2.x, IEPS, q1.x) - m);
            s += __expf(fmaf(f2.y, IEPS, q1.y) - m);
            s += __expf(fmaf(f3.x, IEPS, q1.z) - m);
            s += __expf(fmaf(f3.y, IEPS, q1.w) - m);
        }
    }
    #pragma unroll
    for (int off = 16; off; off >>= 1)
        s += __shfl_xor_sync(0xffffffffu, s, off);

    if (lane == 0) {
        float pn = LMU - (m + __logf(s));
        float po = g_p[row];
        g_p[row] = pn;
        werr[w]  = EPS_F * fabsf(pn - po);   // |u_new - u_old|
    }
    __syncthreads();
    if (tid == 0) {
        float e = 0.0f;
        #pragma unroll
        for (int k = 0; k < 8; k++) e += werr[k];
        g_errpart[blockIdx.x] = e;
    }
}

// ---------------------------------------------------------------------------
// col pass partials: LSE_i(p_i + 10*D_ij) over 1024-row halves.
// grid 128 x 1024: block = (b, 128-col tile, split). lane owns 4 cols;
// warp covers 32 rows; group-max skip avoids exp on negligible 8-row groups.
// ---------------------------------------------------------------------------
__global__ __launch_bounds__(1024) void k_qcol() {
    if (*(volatile int*)&g_done) return;
    __shared__ float ps[NP];
    __shared__ float smM[32][128];
    __shared__ float smS[32][128];

    int tid   = threadIdx.x;
    int bid   = blockIdx.x;
    int split = bid & 1;
    int tile  = (bid >> 1) & 15;
    int b     = bid >> 5;

    for (int i = tid; i < NP; i += 1024) ps[i] = g_p[b * NP + i];
    __syncthreads();

    int w = tid >> 5, lane = tid & 31;
    int r0 = split * 1024 + w * 32;
    const uint2* Db = (const uint2*)(g_D + (size_t)b * NP * NP + tile * 128) + lane;

    float4 m4 = make_float4(-INFINITY, -INFINITY, -INFINITY, -INFINITY);
    float4 s4 = make_float4(0.0f, 0.0f, 0.0f, 0.0f);

    #pragma unroll 1
    for (int c = 0; c < 4; c++) {
        uint2 Lr[8];
        int rb = r0 + c * 8;
        #pragma unroll
        for (int k = 0; k < 8; k++)
            Lr[k] = __ldg(Db + (size_t)(rb + k) * (NP / 4));
        float pv[8];
        #pragma unroll
        for (int k = 0; k < 8; k++) pv[k] = ps[rb + k];

        float ax[8], ay[8];
        // half2 0: cols lane*4 + {0,1}
        #pragma unroll
        for (int k = 0; k < 8; k++) {
            float2 f = h2f(Lr[k].x);
            ax[k] = fmaf(f.x, IEPS, pv[k]);
            ay[k] = fmaf(f.y, IEPS, pv[k]);
        }
        {
            float gx = ax[0], gy = ay[0];
            #pragma unroll
            for (int k = 1; k < 8; k++) { gx = fmaxf(gx, ax[k]); gy = fmaxf(gy, ay[k]); }
            if (__any_sync(0xffffffffu,
                           (gx > m4.x - SKIP_T) | (gy > m4.y - SKIP_T))) {
                float nm = fmaxf(m4.x, gx);
                s4.x *= __expf(m4.x - nm);
                #pragma unroll
                for (int k = 0; k < 8; k++) s4.x += __expf(ax[k] - nm);
                m4.x = nm;
                nm = fmaxf(m4.y, gy);
                s4.y *= __expf(m4.y - nm);
                #pragma unroll
                for (int k = 0; k < 8; k++) s4.y += __expf(ay[k] - nm);
                m4.y = nm;
            }
        }
        // half2 1: cols lane*4 + {2,3}
        #pragma unroll
        for (int k = 0; k < 8; k++) {
            float2 f = h2f(Lr[k].y);
            ax[k] = fmaf(f.x, IEPS, pv[k]);
            ay[k] = fmaf(f.y, IEPS, pv[k]);
        }
        {
            float gx = ax[0], gy = ay[0];
            #pragma unroll
            for (int k = 1; k < 8; k++) { gx = fmaxf(gx, ax[k]); gy = fmaxf(gy, ay[k]); }
            if (__any_sync(0xffffffffu,
                           (gx > m4.z - SKIP_T) | (gy > m4.w - SKIP_T))) {
                float nm = fmaxf(m4.z, gx);
                s4.z *= __expf(m4.z - nm);
                #pragma unroll
                for (int k = 0; k < 8; k++) s4.z += __expf(ax[k] - nm);
                m4.z = nm;
                nm = fmaxf(m4.w, gy);
                s4.w *= __expf(m4.w - nm);
                #pragma unroll
                for (int k = 0; k < 8; k++) s4.w += __expf(ay[k] - nm);
                m4.w = nm;
            }
        }
    }

    *(float4*)&smM[w][lane * 4] = m4;
    *(float4*)&smS[w][lane * 4] = s4;
    __syncthreads();

    if (tid < 128) {
        float M = smM[0][tid];
        #pragma unroll
        for (int k = 1; k < 32; k++) M = fmaxf(M, smM[k][tid]);
        float S = 0.0f;
        #pragma unroll
        for (int k = 0; k < 32; k++) S += smS[k][tid] * __expf(smM[k][tid] - M);
        int col = b * NP + tile * 128 + tid;
        g_qm[split][col] = M;
        g_qs[split][col] = S;
    }
}

// ---------------------------------------------------------------------------
// finalize: q_j = LMU - LSE over both splits; block 0 reduces err -> g_done
// ---------------------------------------------------------------------------
__global__ __launch_bounds__(512) void k_qfin() {
    if (*(volatile int*)&g_done) return;
    int t = blockIdx.x * 512 + threadIdx.x;        // 0..8191
    float m0 = g_qm[0][t], m1 = g_qm[1][t];
    float M  = fmaxf(m0, m1);
    float S  = g_qs[0][t] * __expf(m0 - M) + g_qs[1][t] * __expf(m1 - M);
    g_q[t] = LMU - (M + __logf(S));

    if (blockIdx.x == 0) {
        __shared__ float red[512];
        int tid = threadIdx.x;
        red[tid] = g_errpart[tid] + g_errpart[tid + 512];
        __syncthreads();
        #pragma unroll
        for (int st = 256; st; st >>= 1) {
            if (tid < st) red[tid] += red[tid + st];
            __syncthreads();
        }
        if (tid == 0)
            g_done = (red[0] * (1.0f / (float)NB) < THRESH_F) ? 1 : 0;
    }
}

// ---------------------------------------------------------------------------
// final: cost = sum_ij exp(p_i + q_j + 10D) * (nx_i + ny_j - D)
// ---------------------------------------------------------------------------
__global__ __launch_bounds__(256) void k_final() {
    __shared__ __align__(16) float qs[NP];
    __shared__ __align__(16) float nys[NP];
    __shared__ float wsum[8];

    int tid = threadIdx.x;
    int rowbase = blockIdx.x * 8;
    int b = rowbase >> 11;

    for (int j = tid; j < NP; j += 256) {
        qs[j]  = g_q[b * NP + j];
        nys[j] = g_ny[b * NP + j];
    }
    __syncthreads();

    int w = tid >> 5, lane = tid & 31;
    int row = rowbase + w;
    const uint4* Dr = (const uint4*)(g_D + (size_t)row * NP);
    float pe = g_p[row];
    float nx = g_nx[row];

    float acc = 0.0f;
    #pragma unroll 1
    for (int c = 0; c < 8; c++) {
        uint4 L = __ldg(Dr + c * 32 + lane);
        int jb = (c * 32 + lane) * 8;
        float2 f[4] = {h2f(L.x), h2f(L.y), h2f(L.z), h2f(L.w)};
        #pragma unroll
        for (int k = 0; k < 4; k++) {
            float d0 = f[k].x, d1 = f[k].y;
            int j0 = jb + k * 2;
            float e0 = __expf(pe + qs[j0]     + d0 * IEPS);
            float e1 = __expf(pe + qs[j0 + 1] + d1 * IEPS);
            acc = fmaf(e0, nx + nys[j0]     - d0, acc);
            acc = fmaf(e1, nx + nys[j0 + 1] - d1, acc);
        }
    }
    #pragma unroll
    for (int off = 16; off; off >>= 1)
        acc += __shfl_down_sync(0xffffffffu, acc, off);
    if (lane == 0) wsum[w] = acc;
    __syncthreads();
    if (tid == 0) {
        float e = 0.0f;
        #pragma unroll
        for (int k = 0; k < 8; k++) e += wsum[k];
        g_costpart[blockIdx.x] = e;
    }
}

__global__ void k_reduce(float* out) {
    __shared__ float red[256];
    int tid = threadIdx.x;
    float e = 0.0f;
    for (int k = tid; k < 1024; k += 256) e += g_costpart[k];
    red[tid] = e;
    __syncthreads();
    for (int st = 128; st; st >>= 1) {
        if (tid < st) red[tid] += red[tid + st];
        __syncthreads();
    }
    if (tid == 0) out[0] = red[0] * (1.0f / (float)NB);
}

// ---------------------------------------------------------------------------
extern "C" void kernel_launch(void* const* d_in, const int* in_sizes, int n_in,
                              void* d_out, int out_size) {
    const float* x = (const float*)d_in[0];
    const float* y = (const float*)d_in[1];
    float* out = (float*)d_out;

    k_nxny<<<2048, 256>>>(x, y);
    k_init<<<32, 256>>>();
    dim3 gc(32, 32, 4);
    k_costd<<<gc, 256>>>(x, y);
    for (int it = 0; it < MAX_ITER; ++it) {
        k_prow<<<1024, 256>>>();
        k_qcol<<<128, 1024>>>();
        k_qfin<<<16, 512>>>();
    }
    k_final<<<1024, 256>>>();
    k_reduce<<<1, 256>>>(out);
}

// round 12
// speedup vs baseline: 1.3549x; 1.3549x over previous
#include <cuda_runtime.h>
#include <cuda_fp16.h>
#include <math.h>
#include <string.h>

#define NB 4
#define NP 2048
#define ND 64
#define EPS_F 0.1f
#define IEPS 10.0f
#define THRESH_F 0.1f
#define MAX_ITER 50
#define SKIP_T 22.0f
#define LMU (-7.6245985f)   // log(1/2048 + 1e-8)

// D[b][i][j] = 2 * <x_bi, y_bj>  fp16 (32 MB). All sweeps touch only D.
static __device__ __half g_D[(size_t)NB * NP * NP];
static __device__ float g_nx[NB * NP], g_ny[NB * NP];
static __device__ float g_p[NB * NP];          // p = (u - nx)/eps
static __device__ float g_q[NB * NP];          // q = (v - ny)/eps
static __device__ float g_qm[2][NB * NP];      // col-pass partial max
static __device__ float g_qs[2][NB * NP];      // col-pass partial sum
static __device__ float g_errpart[1024];
static __device__ float g_costpart[1024];
static __device__ int   g_done;

__device__ __forceinline__ float2 h2f(unsigned u) {
    __half2 h; memcpy(&h, &u, 4);
    return __half22float2(h);
}
__device__ __forceinline__ __half2 u2h(unsigned u) {
    __half2 h; memcpy(&h, &u, 4);
    return h;
}

// ---------------------------------------------------------------------------
// squared norms; warp per row, 16384 warps (x then y)
// ---------------------------------------------------------------------------
__global__ __launch_bounds__(256) void k_nxny(const float* __restrict__ x,
                                              const float* __restrict__ y) {
    int gw   = (blockIdx.x * 256 + threadIdx.x) >> 5;
    int lane = threadIdx.x & 31;
    const float* src = (gw < NB * NP) ? x + (size_t)gw * ND
                                      : y + (size_t)(gw - NB * NP) * ND;
    float2 v = ((const float2*)src)[lane];
    float s = v.x * v.x + v.y * v.y;
    #pragma unroll
    for (int off = 16; off; off >>= 1)
        s += __shfl_down_sync(0xffffffffu, s, off);
    if (lane == 0) {
        if (gw < NB * NP) g_nx[gw] = s;
        else              g_ny[gw - NB * NP] = s;
    }
}

// init (after k_nxny): u=v=0  ->  p = -10*nx, q = -10*ny
__global__ void k_init() {
    int t = blockIdx.x * blockDim.x + threadIdx.x;
    if (t < NB * NP) {
        g_p[t] = -IEPS * g_nx[t];
        g_q[t] = -IEPS * g_ny[t];
    }
    if (t == 0) g_done = 0;
}

// ---------------------------------------------------------------------------
// D = 2<x,y> fp16; grid (32,32,4), 256 thr, 64x64 tile
// ---------------------------------------------------------------------------
__global__ __launch_bounds__(256) void k_costd(const float* __restrict__ x,
                                               const float* __restrict__ y) {
    __shared__ __align__(16) float xs[ND][68];
    __shared__ __align__(16) float ys[ND][68];

    int b  = blockIdx.z;
    int i0 = blockIdx.y * 64;
    int j0 = blockIdx.x * 64;
    int tid = threadIdx.x;

    const float* xp = x + ((size_t)b * NP + i0) * ND;
    const float* yp = y + ((size_t)b * NP + j0) * ND;

    for (int idx = tid; idx < 64 * ND; idx += 256) {
        int r = idx >> 6;
        int d = idx & 63;
        xs[d][r] = xp[r * ND + d];
        ys[d][r] = yp[r * ND + d];
    }
    __syncthreads();

    int tx = tid & 15, ty = tid >> 4;
    float acc[4][4] = {};
    #pragma unroll 16
    for (int d = 0; d < ND; d++) {
        float4 xr = *(const float4*)&xs[d][ty * 4];
        float4 yr = *(const float4*)&ys[d][tx * 4];
        float xa[4] = {xr.x, xr.y, xr.z, xr.w};
        float ya[4] = {yr.x, yr.y, yr.z, yr.w};
        #pragma unroll
        for (int a = 0; a < 4; a++)
            #pragma unroll
            for (int c = 0; c < 4; c++)
                acc[a][c] = fmaf(xa[a], ya[c], acc[a][c]);
    }

    #pragma unroll
    for (int a = 0; a < 4; a++) {
        int i = i0 + ty * 4 + a;
        size_t base = ((size_t)b * NP + i) * NP + j0 + tx * 4;
        __half2 h01 = __floats2half2_rn(2.0f * acc[a][0], 2.0f * acc[a][1]);
        __half2 h23 = __floats2half2_rn(2.0f * acc[a][2], 2.0f * acc[a][3]);
        uint2 o;
        memcpy(&o.x, &h01, 4);
        memcpy(&o.y, &h23, 4);
        *(uint2*)(g_D + base) = o;
    }
}

// ---------------------------------------------------------------------------
// row pass: p_new_i = LMU - LSE_j(q_j + 10*D_ij)
// grid 1024 x 256, warp/row. R10 structure: all 8 uint4 D loads batched and
// held live (MLP=8); pass A max in fp16 (HFMA2/HMAX2); pass B fp32 exp only
// on stripes within SKIP_T of the row max, consuming the live registers.
// ---------------------------------------------------------------------------
__global__ __launch_bounds__(256, 3) void k_prow() {
    if (*(volatile int*)&g_done) return;
    __shared__ __align__(16) float    qs[NP];        // fp32 q (pass B)
    __shared__ __align__(16) unsigned qh[NP / 2];    // half2 q (pass A)
    __shared__ float werr[8];

    int tid = threadIdx.x;
    int rowbase = blockIdx.x * 8;
    int b = rowbase >> 11;

    {   // coalesced q load + half2 mirror
        const float4* src = (const float4*)(g_q + b * NP);
        #pragma unroll
        for (int k = 0; k < 2; k++) {
            float4 v = src[tid + k * 256];
            ((float4*)qs)[tid + k * 256] = v;
            __half2 h01 = __floats2half2_rn(v.x, v.y);
            __half2 h23 = __floats2half2_rn(v.z, v.w);
            uint2 o;
            memcpy(&o.x, &h01, 4);
            memcpy(&o.y, &h23, 4);
            ((uint2*)qh)[tid + k * 256] = o;
        }
    }
    __syncthreads();

    int w = tid >> 5, lane = tid & 31;
    int row = rowbase + w;
    const uint4* Dr  = (const uint4*)(g_D + (size_t)row * NP);
    const uint4* qh4 = (const uint4*)qh;
    const float4* qv = (const float4*)qs;

    // batched loads: all 8 in flight (the thing R11 broke)
    uint4 L[8];
    #pragma unroll
    for (int k = 0; k < 8; k++) L[k] = __ldg(Dr + k * 32 + lane);

    const __half2 ieps2 = __floats2half2_rn(IEPS, IEPS);

    // pass A: per-chunk approximate max in fp16
    float cmf[8];
    float m = -INFINITY;
    #pragma unroll
    for (int k = 0; k < 8; k++) {
        uint4 Q = qh4[k * 32 + lane];
        __half2 a0 = __hfma2(u2h(L[k].x), ieps2, u2h(Q.x));
        __half2 a1 = __hfma2(u2h(L[k].y), ieps2, u2h(Q.y));
        __half2 a2 = __hfma2(u2h(L[k].z), ieps2, u2h(Q.z));
        __half2 a3 = __hfma2(u2h(L[k].w), ieps2, u2h(Q.w));
        __half2 c  = __hmax2(__hmax2(a0, a1), __hmax2(a2, a3));
        float cf = fmaxf(__low2float(c), __high2float(c));
        cmf[k] = cf;
        m = fmaxf(m, cf);
    }
    #pragma unroll
    for (int off = 16; off; off >>= 1)
        m = fmaxf(m, __shfl_xor_sync(0xffffffffu, m, off));
    m += 1.0f;   // fp16 max may undershoot true max; pad (LSE stays exact)

    // pass B: fp32 selective exp from live registers
    float s = 0.0f;
    float thr = m - SKIP_T;
    #pragma unroll
    for (int k = 0; k < 8; k++) {
        if (__any_sync(0xffffffffu, cmf[k] > thr)) {
            int qi = (k * 32 + lane) * 2;
            float4 q0 = qv[qi], q1 = qv[qi + 1];
            float2 f0 = h2f(L[k].x), f1 = h2f(L[k].y);
            float2 f2 = h2f(L[k].z), f3 = h2f(L[k].w);
            s += __expf(fmaf(f0.x, IEPS, q0.x) - m);
            s += __expf(fmaf(f0.y, IEPS, q0.y) - m);
            s += __expf(fmaf(f1.x, IEPS, q0.z) - m);
            s += __expf(fmaf(f1.y, IEPS, q0.w) - m);
            s += __expf(fmaf(f2.x, IEPS, q1.x) - m);
            s += __expf(fmaf(f2.y, IEPS, q1.y) - m);
            s += __expf(fmaf(f3.x, IEPS, q1.z) - m);
            s += __expf(fmaf(f3.y, IEPS, q1.w) - m);
        }
    }
    #pragma unroll
    for (int off = 16; off; off >>= 1)
        s += __shfl_xor_sync(0xffffffffu, s, off);

    if (lane == 0) {
        float pn = LMU - (m + __logf(s));
        float po = g_p[row];
        g_p[row] = pn;
        werr[w]  = EPS_F * fabsf(pn - po);   // |u_new - u_old|
    }
    __syncthreads();
    if (tid == 0) {
        float e = 0.0f;
        #pragma unroll
        for (int k = 0; k < 8; k++) e += werr[k];
        g_errpart[blockIdx.x] = e;
    }
}

// ---------------------------------------------------------------------------
// col pass partials: LSE_i(p_i + 10*D_ij) over 1024-row halves.
// grid 128 x 1024: block = (b, 128-col tile, split). lane owns 4 cols;
// warp covers 32 rows; group-max skip avoids exp on negligible 8-row groups.
// ---------------------------------------------------------------------------
__global__ __launch_bounds__(1024) void k_qcol() {
    if (*(volatile int*)&g_done) return;
    __shared__ float ps[NP];
    __shared__ float smM[32][128];
    __shared__ float smS[32][128];

    int tid   = threadIdx.x;
    int bid   = blockIdx.x;
    int split = bid & 1;
    int tile  = (bid >> 1) & 15;
    int b     = bid >> 5;

    for (int i = tid; i < NP; i += 1024) ps[i] = g_p[b * NP + i];
    __syncthreads();

    int w = tid >> 5, lane = tid & 31;
    int r0 = split * 1024 + w * 32;
    const uint2* Db = (const uint2*)(g_D + (size_t)b * NP * NP + tile * 128) + lane;

    float4 m4 = make_float4(-INFINITY, -INFINITY, -INFINITY, -INFINITY);
    float4 s4 = make_float4(0.0f, 0.0f, 0.0f, 0.0f);

    #pragma unroll 1
    for (int c = 0; c < 4; c++) {
        uint2 Lr[8];
        int rb = r0 + c * 8;
        #pragma unroll
        for (int k = 0; k < 8; k++)
            Lr[k] = __ldg(Db + (size_t)(rb + k) * (NP / 4));
        float pv[8];
        #pragma unroll
        for (int k = 0; k < 8; k++) pv[k] = ps[rb + k];

        float ax[8], ay[8];
        // half2 0: cols lane*4 + {0,1}
        #pragma unroll
        for (int k = 0; k < 8; k++) {
            float2 f = h2f(Lr[k].x);
            ax[k] = fmaf(f.x, IEPS, pv[k]);
            ay[k] = fmaf(f.y, IEPS, pv[k]);
        }
        {
            float gx = ax[0], gy = ay[0];
            #pragma unroll
            for (int k = 1; k < 8; k++) { gx = fmaxf(gx, ax[k]); gy = fmaxf(gy, ay[k]); }
            if (__any_sync(0xffffffffu,
                           (gx > m4.x - SKIP_T) | (gy > m4.y - SKIP_T))) {
                float nm = fmaxf(m4.x, gx);
                s4.x *= __expf(m4.x - nm);
                #pragma unroll
                for (int k = 0; k < 8; k++) s4.x += __expf(ax[k] - nm);
                m4.x = nm;
                nm = fmaxf(m4.y, gy);
                s4.y *= __expf(m4.y - nm);
                #pragma unroll
                for (int k = 0; k < 8; k++) s4.y += __expf(ay[k] - nm);
                m4.y = nm;
            }
        }
        // half2 1: cols lane*4 + {2,3}
        #pragma unroll
        for (int k = 0; k < 8; k++) {
            float2 f = h2f(Lr[k].y);
            ax[k] = fmaf(f.x, IEPS, pv[k]);
            ay[k] = fmaf(f.y, IEPS, pv[k]);
        }
        {
            float gx = ax[0], gy = ay[0];
            #pragma unroll
            for (int k = 1; k < 8; k++) { gx = fmaxf(gx, ax[k]); gy = fmaxf(gy, ay[k]); }
            if (__any_sync(0xffffffffu,
                           (gx > m4.z - SKIP_T) | (gy > m4.w - SKIP_T))) {
                float nm = fmaxf(m4.z, gx);
                s4.z *= __expf(m4.z - nm);
                #pragma unroll
                for (int k = 0; k < 8; k++) s4.z += __expf(ax[k] - nm);
                m4.z = nm;
                nm = fmaxf(m4.w, gy);
                s4.w *= __expf(m4.w - nm);
                #pragma unroll
                for (int k = 0; k < 8; k++) s4.w += __expf(ay[k] - nm);
                m4.w = nm;
            }
        }
    }

    *(float4*)&smM[w][lane * 4] = m4;
    *(float4*)&smS[w][lane * 4] = s4;
    __syncthreads();

    if (tid < 128) {
        float M = smM[0][tid];
        #pragma unroll
        for (int k = 1; k < 32; k++) M = fmaxf(M, smM[k][tid]);
        float S = 0.0f;
        #pragma unroll
        for (int k = 0; k < 32; k++) S += smS[k][tid] * __expf(smM[k][tid] - M);
        int col = b * NP + tile * 128 + tid;
        g_qm[split][col] = M;
        g_qs[split][col] = S;
    }
}

// ---------------------------------------------------------------------------
// finalize: q_j = LMU - LSE over both splits; block 0 reduces err -> g_done
// ---------------------------------------------------------------------------
__global__ __launch_bounds__(512) void k_qfin() {
    if (*(volatile int*)&g_done) return;
    int t = blockIdx.x * 512 + threadIdx.x;        // 0..8191
    float m0 = g_qm[0][t], m1 = g_qm[1][t];
    float M  = fmaxf(m0, m1);
    float S  = g_qs[0][t] * __expf(m0 - M) + g_qs[1][t] * __expf(m1 - M);
    g_q[t] = LMU - (M + __logf(S));

    if (blockIdx.x == 0) {
        __shared__ float red[512];
        int tid = threadIdx.x;
        red[tid] = g_errpart[tid] + g_errpart[tid + 512];
        __syncthreads();
        #pragma unroll
        for (int st = 256; st; st >>= 1) {
            if (tid < st) red[tid] += red[tid + st];
            __syncthreads();
        }
        if (tid == 0)
            g_done = (red[0] * (1.0f / (float)NB) < THRESH_F) ? 1 : 0;
    }
}

// ---------------------------------------------------------------------------
// final: cost = sum_ij exp(p_i + q_j + 10D) * (nx_i + ny_j - D)
// ---------------------------------------------------------------------------
__global__ __launch_bounds__(256) void k_final() {
    __shared__ __align__(16) float qs[NP];
    __shared__ __align__(16) float nys[NP];
    __shared__ float wsum[8];

    int tid = threadIdx.x;
    int rowbase = blockIdx.x * 8;
    int b = rowbase >> 11;

    for (int j = tid; j < NP; j += 256) {
        qs[j]  = g_q[b * NP + j];
        nys[j] = g_ny[b * NP + j];
    }
    __syncthreads();

    int w = tid >> 5, lane = tid & 31;
    int row = rowbase + w;
    const uint4* Dr = (const uint4*)(g_D + (size_t)row * NP);
    float pe = g_p[row];
    float nx = g_nx[row];

    float acc = 0.0f;
    #pragma unroll 1
    for (int c = 0; c < 8; c++) {
        uint4 L = __ldg(Dr + c * 32 + lane);
        int jb = (c * 32 + lane) * 8;
        float2 f[4] = {h2f(L.x), h2f(L.y), h2f(L.z), h2f(L.w)};
        #pragma unroll
        for (int k = 0; k < 4; k++) {
            float d0 = f[k].x, d1 = f[k].y;
            int j0 = jb + k * 2;
            float e0 = __expf(pe + qs[j0]     + d0 * IEPS);
            float e1 = __expf(pe + qs[j0 + 1] + d1 * IEPS);
            acc = fmaf(e0, nx + nys[j0]     - d0, acc);
            acc = fmaf(e1, nx + nys[j0 + 1] - d1, acc);
        }
    }
    #pragma unroll
    for (int off = 16; off; off >>= 1)
        acc += __shfl_down_sync(0xffffffffu, acc, off);
    if (lane == 0) wsum[w] = acc;
    __syncthreads();
    if (tid == 0) {
        float e = 0.0f;
        #pragma unroll
        for (int k = 0; k < 8; k++) e += wsum[k];
        g_costpart[blockIdx.x] = e;
    }
}

__global__ void k_reduce(float* out) {
    __shared__ float red[256];
    int tid = threadIdx.x;
    float e = 0.0f;
    for (int k = tid; k < 1024; k += 256) e += g_costpart[k];
    red[tid] = e;
    __syncthreads();
    for (int st = 128; st; st >>= 1) {
        if (tid < st) red[tid] += red[tid + st];
        __syncthreads();
    }
    if (tid == 0) out[0] = red[0] * (1.0f / (float)NB);
}

// ---------------------------------------------------------------------------
extern "C" void kernel_launch(void* const* d_in, const int* in_sizes, int n_in,
                              void* d_out, int out_size) {
    const float* x = (const float*)d_in[0];
    const float* y = (const float*)d_in[1];
    float* out = (float*)d_out;

    k_nxny<<<2048, 256>>>(x, y);
    k_init<<<32, 256>>>();
    dim3 gc(32, 32, 4);
    k_costd<<<gc, 256>>>(x, y);
    for (int it = 0; it < MAX_ITER; ++it) {
        k_prow<<<1024, 256>>>();
        k_qcol<<<128, 1024>>>();
        k_qfin<<<16, 512>>>();
    }
    k_final<<<1024, 256>>>();
    k_reduce<<<1, 256>>>(out);
}